// round 1
// baseline (speedup 1.0000x reference)
#include <cuda_runtime.h>

// Shapes (fixed by the problem)
#define Bn   8
#define NIN  4096
#define DIN  128
#define KOUT 256

#define ADJ_PER_B  (NIN * NIN)          // 16,777,216
#define ADJ_TOTAL  (Bn * ADJ_PER_B)     // 134,217,728 floats (512 MB)

// Grid geometry for the big reduction
#define ADJ_BLOCKS   2048               // 256 blocks per batch, 65536 elems each
#define NODE_BLOCKS  128                // 16 per batch, 256 n-rows each
#define RTHREADS     256

// Scratch (no allocations allowed -> __device__ globals)
__device__ double g_adj_sum[Bn];
__device__ float  g_node_sum[Bn * DIN];

// ---------------------------------------------------------------------------
// Kernel 1: zero the accumulators (must be deterministic every launch)
// ---------------------------------------------------------------------------
__global__ void mp_init_kernel() {
    int t = threadIdx.x;
    if (t < Bn) g_adj_sum[t] = 0.0;
    for (int i = t; i < Bn * DIN; i += blockDim.x) g_node_sum[i] = 0.0f;
}

// ---------------------------------------------------------------------------
// Kernel 2: blocks [0, ADJ_BLOCKS)            -> total sum of adj per batch
//           blocks [ADJ_BLOCKS, +NODE_BLOCKS) -> column-sum of node_set per batch
// C == ones exactly (softmax over a size-1 axis), so these two reductions are
// the entire data-dependent work of the layer.
// ---------------------------------------------------------------------------
__global__ void mp_reduce_kernel(const float* __restrict__ adj,
                                 const float* __restrict__ node) {
    const int bid = blockIdx.x;

    if (bid < ADJ_BLOCKS) {
        // ---- adj total-sum: contiguous 65536-element chunk per block ----
        const int f4_per_block = (ADJ_TOTAL / ADJ_BLOCKS) / 4;   // 16384 float4
        const float4* __restrict__ base =
            reinterpret_cast<const float4*>(adj) + (size_t)bid * f4_per_block;

        float acc = 0.0f;   // per-thread: 64 float4 = 256 uniforms in [0,1); fp32 is plenty
        #pragma unroll 4
        for (int i = threadIdx.x; i < f4_per_block; i += RTHREADS) {
            float4 v = base[i];
            acc += (v.x + v.y) + (v.z + v.w);
        }

        __shared__ double sd[RTHREADS];
        sd[threadIdx.x] = (double)acc;
        __syncthreads();
        for (int s = RTHREADS / 2; s > 0; s >>= 1) {
            if (threadIdx.x < s) sd[threadIdx.x] += sd[threadIdx.x + s];
            __syncthreads();
        }
        if (threadIdx.x == 0) {
            int b = bid / (ADJ_BLOCKS / Bn);                     // 256 blocks / batch
            atomicAdd(&g_adj_sum[b], sd[0]);
        }
    } else {
        // ---- node_set column sum: 256 n-rows per block ----
        const int nb      = bid - ADJ_BLOCKS;                    // 0..127
        const int per_b   = NODE_BLOCKS / Bn;                    // 16
        const int b       = nb / per_b;
        const int sub     = nb % per_b;
        const int rows    = NIN / per_b;                         // 256
        const int row0    = sub * rows;
        const float* __restrict__ base = node + ((size_t)b * NIN + row0) * DIN;

        const int d      = threadIdx.x & (DIN - 1);
        const int stripe = threadIdx.x >> 7;                     // 0 or 1 (128 rows each)

        float acc = 0.0f;
        #pragma unroll 4
        for (int r = stripe * 128; r < stripe * 128 + 128; r++)
            acc += base[(size_t)r * DIN + d];

        __shared__ float sf[DIN];
        if (stripe == 0) sf[d] = acc;
        __syncthreads();
        if (stripe == 1) atomicAdd(&g_node_sum[b * DIN + d], acc + sf[d]);
    }
}

// ---------------------------------------------------------------------------
// Kernel 3: finalize.
//   new_node_set[b,k,:] = lrelu(colsum(node_set[b]) @ lin_w + lin_b)  (same all k)
//   new_adj[b,k,j]      = total_sum(adj[b])                           (same all k,j)
// Output layout: [new_node_set (8,256,128) | new_adj (8,256,256)] fp32.
// ---------------------------------------------------------------------------
#define FIN_SUB 16    // sub-blocks per batch (for write bandwidth)

__global__ void mp_finalize_kernel(const float* __restrict__ lin_w,
                                   const float* __restrict__ lin_b,
                                   float* __restrict__ out) {
    const int b   = blockIdx.x / FIN_SUB;
    const int sub = blockIdx.x % FIN_SUB;
    const int t   = threadIdx.x;

    __shared__ float r[DIN];

    if (t < DIN) {
        float acc = lin_b[t];
        const float* __restrict__ s = &g_node_sum[b * DIN];
        #pragma unroll 8
        for (int d = 0; d < DIN; d++)
            acc = fmaf(s[d], lin_w[d * DIN + t], acc);   // column read, coalesced over t
        r[t] = (acc >= 0.0f) ? acc : 0.01f * acc;
    }
    __syncthreads();

    const float aval = (float)g_adj_sum[b];

    // --- node region: batch b spans KOUT*DIN = 32768 floats = 8192 float4 ---
    {
        float4* __restrict__ node_out =
            reinterpret_cast<float4*>(out) + (size_t)b * (KOUT * DIN / 4);
        const float4* __restrict__ r4 = reinterpret_cast<const float4*>(r);
        const int f4_total = KOUT * DIN / 4;          // 8192
        const int per      = f4_total / FIN_SUB;      // 512
        for (int i = t; i < per; i += blockDim.x) {
            int idx = sub * per + i;
            node_out[idx] = r4[idx & (DIN / 4 - 1)];  // row of 32 float4, repeated
        }
    }

    // --- adj region: batch b spans KOUT*KOUT = 65536 floats = 16384 float4 ---
    {
        float4* __restrict__ adj_out =
            reinterpret_cast<float4*>(out + (size_t)Bn * KOUT * DIN) +
            (size_t)b * (KOUT * KOUT / 4);
        const float4 av4 = make_float4(aval, aval, aval, aval);
        const int f4_total = KOUT * KOUT / 4;         // 16384
        const int per      = f4_total / FIN_SUB;      // 1024
        float4* __restrict__ base = adj_out + (size_t)sub * per;
        for (int i = t; i < per; i += blockDim.x)
            base[i] = av4;
    }
}

// ---------------------------------------------------------------------------
// Launch. Inputs (metadata order): node_set, adj, centroids, conv_w, conv_b,
// lin_w, lin_b. centroids/conv_* are mathematically dead (softmax over a
// size-1 axis makes C identically 1), so they are never read.
// ---------------------------------------------------------------------------
extern "C" void kernel_launch(void* const* d_in, const int* in_sizes, int n_in,
                              void* d_out, int out_size) {
    const float* node  = (const float*)d_in[0];
    const float* adj   = (const float*)d_in[1];
    // d_in[2] centroids, d_in[3] conv_w, d_in[4] conv_b: unused (exactly dead)
    const float* lin_w = (const float*)d_in[5];
    const float* lin_b = (const float*)d_in[6];
    float* out = (float*)d_out;

    mp_init_kernel<<<1, 128>>>();
    mp_reduce_kernel<<<ADJ_BLOCKS + NODE_BLOCKS, RTHREADS>>>(adj, node);
    mp_finalize_kernel<<<Bn * FIN_SUB, 256>>>(lin_w, lin_b, out);
}